// round 1
// baseline (speedup 1.0000x reference)
#include <cuda_runtime.h>

#define Bn 2048
#define Tn 512
#define Hn 16
#define Ln 8

typedef unsigned long long ull;

// Ping-pong scratch for inter-layer hidden sequences (64 MB each).
__device__ float g_bufA[(size_t)Bn * Tn * Hn];
__device__ float g_bufB[(size_t)Bn * Tn * Hn];

// ---- packed fp32x2 FMA (Blackwell): d = a * b + d ----
__device__ __forceinline__ void ffma2(ull& d, ull a, ull b) {
    asm("fma.rn.f32x2 %0, %1, %2, %0;" : "+l"(d) : "l"(a), "l"(b));
}

__device__ __forceinline__ float2 u2f(ull a) {
    float2 f;
    asm("mov.b64 {%0,%1}, %2;" : "=f"(f.x), "=f"(f.y) : "l"(a));
    return f;
}

// Load 16 contiguous floats as 8 packed f32x2 (4x LDG.128 / LDS.128).
__device__ __forceinline__ void load8(ull* d, const float* p) {
    const ulonglong2* q = (const ulonglong2*)p;
    ulonglong2 v0 = q[0], v1 = q[1], v2 = q[2], v3 = q[3];
    d[0] = v0.x; d[1] = v0.y; d[2] = v1.x; d[3] = v1.y;
    d[4] = v2.x; d[5] = v2.y; d[6] = v3.x; d[7] = v3.y;
}

__device__ __forceinline__ float sigf(float x) {
    // 1 / (1 + e^-x): FMUL + MUFU.EX2 + FADD + MUFU.RCP. Saturates correctly at +-inf.
    return __fdividef(1.0f, 1.0f + __expf(-x));
}
__device__ __forceinline__ float tanhf_fast(float x) {
    // 2/(1+e^-2x) - 1: well-behaved at both infinities (no NaN).
    return __fdividef(2.0f, 1.0f + __expf(-2.0f * x)) - 1.0f;
}

// One LSTM layer over the whole sequence.
// Warp = 2 batch elements (16 lanes each); lane = one hidden unit j, computing
// its 4 gate rows (i=j, f=16+j, g=32+j, o=48+j). Weights live in registers as
// packed f32x2 pairs over the K dim. h is exchanged via double-buffered smem.
__global__ void __launch_bounds__(224, 1)
lstm_layer(const float* __restrict__ in, float* __restrict__ out,
           const float* __restrict__ Wih, const float* __restrict__ Whh,
           const float* __restrict__ bih, const float* __restrict__ bhh)
{
    __shared__ __align__(16) float sh[7][2][2][16];  // [warp][batch-half][parity][h]

    const int warp = threadIdx.x >> 5;
    const int lane = threadIdx.x & 31;
    const int w = blockIdx.x * 7 + warp;
    if (w >= Bn / 2) return;

    const int half = lane >> 4;   // which batch element within the warp
    const int j    = lane & 15;   // hidden unit
    const int b    = 2 * w + half;

    // ---- load weights into registers (packed pairs) ----
    ull wx[4][8], wh[4][8], bias2[4];
#pragma unroll
    for (int q = 0; q < 4; q++) {
        const int row = q * Hn + j;
        load8(wx[q], Wih + row * Hn);
        load8(wh[q], Whh + row * Hn);
        float bb = bih[row] + bhh[row];
        float z = 0.0f;
        asm("mov.b64 %0, {%1,%2};" : "=l"(bias2[q]) : "f"(bb), "f"(z));
    }

    // init h = 0 (slot 0), c = 0
    sh[warp][half][0][j] = 0.0f;
    float c = 0.0f;
    __syncwarp();

    const float* xrow = in  + (size_t)b * Tn * Hn;
    float*       orow = out + (size_t)b * Tn * Hn;

    ull xp[8];
    load8(xp, xrow);  // prefetch t = 0

    for (int t = 0; t < Tn; t++) {
        // prefetch next x while computing (clamped at the tail)
        ull xn[8];
        const int tnext = (t + 1 < Tn) ? (t + 1) : t;
        load8(xn, xrow + tnext * Hn);

        // gather previous h (all 16 values, packed) from smem
        ull hp[8];
        load8(hp, &sh[warp][half][t & 1][0]);

        ull a0 = bias2[0], a1 = bias2[1], a2 = bias2[2], a3 = bias2[3];
#pragma unroll
        for (int i = 0; i < 8; i++) {
            ffma2(a0, wx[0][i], xp[i]);
            ffma2(a1, wx[1][i], xp[i]);
            ffma2(a2, wx[2][i], xp[i]);
            ffma2(a3, wx[3][i], xp[i]);
        }
#pragma unroll
        for (int i = 0; i < 8; i++) {
            ffma2(a0, wh[0][i], hp[i]);
            ffma2(a1, wh[1][i], hp[i]);
            ffma2(a2, wh[2][i], hp[i]);
            ffma2(a3, wh[3][i], hp[i]);
        }
        float2 f0 = u2f(a0), f1 = u2f(a1), f2 = u2f(a2), f3 = u2f(a3);
        const float gi = f0.x + f0.y;
        const float gf = f1.x + f1.y;
        const float gg = f2.x + f2.y;
        const float go = f3.x + f3.y;

        const float si = sigf(gi);
        const float sf = sigf(gf);
        const float tg = tanhf_fast(gg);
        const float so = sigf(go);
        c = sf * c + si * tg;
        const float h = so * tanhf_fast(c);

        sh[warp][half][(t + 1) & 1][j] = h;   // publish for next step
        orow[t * Hn + j] = h;                 // layer output (coalesced 64B/half-warp)
        __syncwarp();

#pragma unroll
        for (int i = 0; i < 8; i++) xp[i] = xn[i];
    }
}

// Readout: position = last @ Wp^T + bp ; orientation = tanh(last @ Wo^T + bo)
__global__ void head_kernel(const float* __restrict__ hbuf,
                            const float* __restrict__ Wp, const float* __restrict__ bp,
                            const float* __restrict__ Wo, const float* __restrict__ bo,
                            float* __restrict__ out)
{
    int b = blockIdx.x * blockDim.x + threadIdx.x;
    if (b >= Bn) return;
    const float* h = hbuf + (size_t)b * Tn * Hn + (size_t)(Tn - 1) * Hn;
    float hv[16];
#pragma unroll
    for (int i = 0; i < 16; i++) hv[i] = h[i];

#pragma unroll
    for (int r = 0; r < 3; r++) {
        float s = bp[r];
#pragma unroll
        for (int k = 0; k < 16; k++) s += hv[k] * Wp[r * 16 + k];
        out[b * 6 + r] = s;
    }
#pragma unroll
    for (int r = 0; r < 3; r++) {
        float s = bo[r];
#pragma unroll
        for (int k = 0; k < 16; k++) s += hv[k] * Wo[r * 16 + k];
        out[b * 6 + 3 + r] = tanhf_fast(s);
    }
}

extern "C" void kernel_launch(void* const* d_in, const int* in_sizes, int n_in,
                              void* d_out, int out_size)
{
    const float* x   = (const float*)d_in[0];
    const float* Wih = (const float*)d_in[1];  // (8, 64, 16)
    const float* Whh = (const float*)d_in[2];  // (8, 64, 16)
    const float* bih = (const float*)d_in[3];  // (8, 64)
    const float* bhh = (const float*)d_in[4];  // (8, 64)
    const float* Wp  = (const float*)d_in[5];  // (3, 16)
    const float* bp  = (const float*)d_in[6];  // (3,)
    const float* Wo  = (const float*)d_in[7];  // (3, 16)
    const float* bo  = (const float*)d_in[8];  // (3,)
    float* out = (float*)d_out;

    float *bufA, *bufB;
    cudaGetSymbolAddress((void**)&bufA, g_bufA);
    cudaGetSymbolAddress((void**)&bufB, g_bufB);

    const dim3 grid((Bn / 2 + 6) / 7);  // 147 blocks x 7 warps = 1029 warps >= 1024
    const dim3 blk(224);

    const float* cur = x;
    for (int l = 0; l < Ln; l++) {
        float* o = (l & 1) ? bufB : bufA;
        lstm_layer<<<grid, blk>>>(cur, o,
                                  Wih + (size_t)l * 64 * Hn,
                                  Whh + (size_t)l * 64 * Hn,
                                  bih + (size_t)l * 64,
                                  bhh + (size_t)l * 64);
        cur = o;
    }
    head_kernel<<<(Bn + 255) / 256, 256>>>(cur, Wp, bp, Wo, bo, out);
}